// round 1
// baseline (speedup 1.0000x reference)
#include <cuda_runtime.h>

// Problem constants
#define IN_CH   2048
#define NUNITS  16
#define USIZE   64
#define NB      32
#define NUIN    16          // in_units (contraction inner dim u)
#define NCOL    1024        // NUNITS*USIZE  (c = j*64 + k)
#define KSPLIT  128
#define ICHUNK  16          // IN_CH / KSPLIT
#define ISTAGE  8

// Scratch (static device globals: no runtime allocation)
__device__ float g_xT[IN_CH * 512];             // 4 MB:  [i][u2*64 + b*2 + p], u = 2*u2+p
__device__ float g_partial[KSPLIT * NB * NCOL]; // 16 MB: [ks][b][c]
__device__ float g_s[NB * NCOL];                // 128 KB: [b][c]

__device__ __forceinline__ unsigned long long ffma2(unsigned long long a,
                                                    unsigned long long b,
                                                    unsigned long long c) {
    unsigned long long d;
    asm("fma.rn.f32x2 %0, %1, %2, %3;" : "=l"(d) : "l"(a), "l"(b), "l"(c));
    return d;
}

__device__ __forceinline__ float add_halves(unsigned long long v) {
    return __uint_as_float((unsigned)(v & 0xffffffffull)) +
           __uint_as_float((unsigned)(v >> 32));
}

// ---------------------------------------------------------------------------
// Kernel 1: transpose x (B, U, IC) -> xT[i][u2*64 + b*2 + p]
// Writes coalesced; reads hit L2 (x = 4 MB resident, each sector reused 8x).
// ---------------------------------------------------------------------------
__global__ void k_transpose(const float* __restrict__ x) {
    int o = blockIdx.x * 256 + threadIdx.x;
    if (o >= IN_CH * 512) return;
    int i  = o >> 9;
    int j  = o & 511;
    int p  = j & 1;
    int b  = (j >> 1) & 31;
    int u2 = j >> 6;
    int u  = 2 * u2 + p;
    g_xT[o] = x[b * (NUIN * IN_CH) + u * IN_CH + i];
}

// ---------------------------------------------------------------------------
// Kernel 2: main GEMM  s[b,c] = sum_{i,u} W[i,c,u] * x[b,u,i]
// Block: 128 thr = 32 col-groups x 4 batch-groups. Thread: 4 cols x 8 batches.
// Accumulators are f32x2 pairs over (even u, odd u) so both W and x pairs are
// memory-contiguous 64-bit loads feeding fma.rn.f32x2 directly.
// Grid: (8 col-blocks, KSPLIT k-splits); each block does ICHUNK=16 i's.
// ---------------------------------------------------------------------------
__global__ void __launch_bounds__(128, 4) k_main(const float* __restrict__ W) {
    __shared__ float xs[ISTAGE * 512];

    const int tid   = threadIdx.x;
    const int bg    = tid & 3;       // batch group: b = bg*8 .. bg*8+7
    const int cg    = tid >> 2;      // column group within block
    const int cb    = blockIdx.x;    // 0..7
    const int ks    = blockIdx.y;    // 0..KSPLIT-1
    const int cbase = cb * 128 + cg * 4;
    const int i0    = ks * ICHUNK;

    unsigned long long acc[4][8];
#pragma unroll
    for (int cc = 0; cc < 4; ++cc)
#pragma unroll
        for (int bb = 0; bb < 8; ++bb) acc[cc][bb] = 0ull;

    for (int st = 0; st < ICHUNK / ISTAGE; ++st) {
        // stage ISTAGE i's of xT into smem (contiguous, coalesced float4)
        const float4* src = (const float4*)(g_xT + (size_t)(i0 + st * ISTAGE) * 512);
        float4* dst = (float4*)xs;
#pragma unroll
        for (int t = tid; t < ISTAGE * 128; t += 128) dst[t] = src[t];
        __syncthreads();

#pragma unroll 4
        for (int ii = 0; ii < ISTAGE; ++ii) {
            const int i = i0 + st * ISTAGE + ii;
            const unsigned long long* xbase =
                (const unsigned long long*)xs + ii * 256 + bg * 8;
            const float* wrow = W + (size_t)i * 16384 + (size_t)cbase * 16;

#pragma unroll
            for (int h = 0; h < 2; ++h) {
                // W pairs for u = 8h .. 8h+7 of this thread's 4 columns
                unsigned long long w[4][4];
#pragma unroll
                for (int cc = 0; cc < 4; ++cc) {
                    const ulonglong2* wp =
                        (const ulonglong2*)(wrow + cc * 16) + h * 2;
                    ulonglong2 a0 = wp[0];
                    ulonglong2 a1 = wp[1];
                    w[cc][0] = a0.x; w[cc][1] = a0.y;
                    w[cc][2] = a1.x; w[cc][3] = a1.y;
                }
#pragma unroll
                for (int q = 0; q < 4; ++q) {
                    const int u2 = h * 4 + q;
                    const ulonglong2* xp = (const ulonglong2*)(xbase + u2 * 32);
                    ulonglong2 x0 = xp[0], x1 = xp[1], x2 = xp[2], x3 = xp[3];
                    unsigned long long xv[8] = { x0.x, x0.y, x1.x, x1.y,
                                                 x2.x, x2.y, x3.x, x3.y };
#pragma unroll
                    for (int cc = 0; cc < 4; ++cc)
#pragma unroll
                        for (int bb = 0; bb < 8; ++bb)
                            acc[cc][bb] = ffma2(w[cc][q], xv[bb], acc[cc][bb]);
                }
            }
        }
        __syncthreads();
    }

    // fold (even-u, odd-u) halves and store partials [ks][b][c] (float4 stores)
#pragma unroll
    for (int bb = 0; bb < 8; ++bb) {
        const int b = bg * 8 + bb;
        float4 v;
        v.x = add_halves(acc[0][bb]);
        v.y = add_halves(acc[1][bb]);
        v.z = add_halves(acc[2][bb]);
        v.w = add_halves(acc[3][bb]);
        *(float4*)(g_partial + (size_t)ks * (NB * NCOL) + (size_t)b * NCOL + cbase) = v;
    }
}

// ---------------------------------------------------------------------------
// Kernel 3: sum K-split partials -> g_s[b][c]   (fully coalesced)
// ---------------------------------------------------------------------------
__global__ void k_reduce() {
    int o = blockIdx.x * 256 + threadIdx.x;   // 0 .. NB*NCOL-1
    float s = 0.f;
    const float* p = g_partial + o;
#pragma unroll 8
    for (int ks = 0; ks < KSPLIT; ++ks) s += p[(size_t)ks * (NB * NCOL)];
    g_s[o] = s;
}

// ---------------------------------------------------------------------------
// Kernel 4: squash per batch. mag_sq sums over the num_units axis j for each
// unit_size component k (faithful to the reference's axis=2 reduction).
// ---------------------------------------------------------------------------
__global__ void k_squash(float* __restrict__ out) {
    const int b = blockIdx.x;
    const int c = threadIdx.x;   // 0..1023, c = j*64 + k
    __shared__ float sd[NCOL];
    __shared__ float mag[USIZE];

    float s = g_s[b * NCOL + c];
    sd[c] = s;
    __syncthreads();

    if (c < USIZE) {
        float m = 0.f;
#pragma unroll
        for (int j = 0; j < NUNITS; ++j) {
            float v = sd[j * USIZE + c];
            m += v * v;
        }
        mag[c] = m;
    }
    __syncthreads();

    float m = mag[c & (USIZE - 1)];
    out[b * NCOL + c] = s * m / ((1.0f + m) * sqrtf(m));
}

// ---------------------------------------------------------------------------
extern "C" void kernel_launch(void* const* d_in, const int* in_sizes, int n_in,
                              void* d_out, int out_size) {
    // metadata order: x (1,048,576 floats), W (33,554,432 floats).
    // Guard by size in case of reordering.
    const float* x = (const float*)d_in[0];
    const float* W = (const float*)d_in[1];
    if (n_in >= 2 && in_sizes[0] > in_sizes[1]) {
        W = (const float*)d_in[0];
        x = (const float*)d_in[1];
    }
    float* out = (float*)d_out;

    k_transpose<<<(IN_CH * 512 + 255) / 256, 256>>>(x);
    dim3 grid_main(8, KSPLIT);
    k_main<<<grid_main, 128>>>(W);
    k_reduce<<<(NB * NCOL) / 256, 256>>>();
    k_squash<<<NB, NCOL>>>(out);
}

// round 3
// speedup vs baseline: 2.2244x; 2.2244x over previous
#include <cuda_runtime.h>
#include <cstdint>

// ---------------------------------------------------------------------------
// s[b,c] = sum_{i,u} W[i,c,u] * x[b,u,i]; out = squash(s)
// GEMM: D[M=1024 c][N=32 b] = A[c,k] B[k,b], k = i*16+u, K = 32768
// Legacy mma.sync.m16n8k8 tf32 (sm_103 plain target; tcgen05 not available).
// ---------------------------------------------------------------------------

#define NB      32
#define NCOL    1024
#define USIZE   64
#define NUNITS  16
#define KS      16        // K-splits (grid.y): 128 i's per CTA
#define CBLK    8         // column blocks of 128 (grid.x)
#define STAGES  32        // K-stages per CTA; stage = 4 i's = 64 k

// smem: A 32KB frag-ready | B 8KB frag-ready, double buffered
#define SM_B_OFF   32768
#define BUF_BYTES  40960
#define SMEM_TOTAL (2 * BUF_BYTES)

// Scratch (static device globals; no runtime allocation)
__device__ float g_Bfrag[2048 * 512];        // 4 MB: frag-ready x, [i][n'][s][lane][e]
__device__ float g_partial[KS * NB * NCOL];  // 2 MB: [ks][b][c]

__device__ __forceinline__ uint32_t f2tf32(float v) {
    uint32_t r;
    asm("cvt.rna.tf32.f32 %0, %1;" : "=r"(r) : "f"(v));
    return r;
}

__device__ __forceinline__ void mma_tf32(float4& d,
                                         uint32_t a0, uint32_t a1,
                                         uint32_t a2, uint32_t a3,
                                         uint32_t b0, uint32_t b1) {
    asm volatile(
        "mma.sync.aligned.m16n8k8.row.col.f32.tf32.tf32.f32 "
        "{%0,%1,%2,%3}, {%4,%5,%6,%7}, {%8,%9}, {%0,%1,%2,%3};"
        : "+f"(d.x), "+f"(d.y), "+f"(d.z), "+f"(d.w)
        : "r"(a0), "r"(a1), "r"(a2), "r"(a3), "r"(b0), "r"(b1));
}

// ---------------------------------------------------------------------------
// Prep: x (B,U,IC) -> g_Bfrag[i][n'][s][lane=4g+t][e] = tf32(x[8n'+g][4t+2s+e][i])
// Writes coalesced; x (4MB) reads scattered but L2-resident.
// ---------------------------------------------------------------------------
__global__ void k_prep(const float* __restrict__ x) {
    int o = blockIdx.x * 256 + threadIdx.x;     // 0 .. 1048575
    int e    = o & 1;
    int lane = (o >> 1) & 31;
    int s    = (o >> 6) & 1;
    int np   = (o >> 7) & 3;
    int i    = o >> 9;
    int g = lane >> 2, t = lane & 3;
    int b = 8 * np + g;
    int u = 4 * t + 2 * s + e;
    float v = x[(size_t)b * 32768 + (size_t)u * 2048 + i];
    g_Bfrag[o] = __uint_as_float(f2tf32(v));
}

// ---------------------------------------------------------------------------
// Main GEMM. grid (CBLK, KS), 256 threads = 8 warps; warp w owns m-tile
// rows [cb*128 + 16w, +16). Per stage: 4 i's. Accumulate K=2048 per CTA.
// ---------------------------------------------------------------------------
__global__ void __launch_bounds__(256, 1) k_main(const float* __restrict__ W) {
    extern __shared__ char sm[];
    const int tid = threadIdx.x;
    const int wr = tid >> 5, l = tid & 31;
    const int g = l >> 2, t = l & 3;
    const int cb = blockIdx.x, ks = blockIdx.y;
    const int i00 = ks * 128;

    // per-thread gmem bases
    // A: W[i][c][u]: c = cb*128 + wr*16 + 8*ci + g, u = 4t..4t+3
    const float* wbase = W + (size_t)(cb * 128 + wr * 16 + g) * 16 + t * 4;
    const float* bbase = g_Bfrag + (size_t)i00 * 512 + tid * 4;

    float4 apre[8];
    float4 bpre[2];
    float4 acc[4];
#pragma unroll
    for (int np = 0; np < 4; ++np) acc[np] = make_float4(0.f, 0.f, 0.f, 0.f);

    // prefetch stage 0
    {
        const float* p = wbase + (size_t)i00 * 16384;
#pragma unroll
        for (int ci = 0; ci < 2; ++ci)
#pragma unroll
            for (int ii = 0; ii < 4; ++ii)
                apre[ci * 4 + ii] = *(const float4*)(p + (size_t)ii * 16384 + ci * 128);
        bpre[0] = *(const float4*)(bbase);
        bpre[1] = *(const float4*)(bbase + 1024);
    }

#pragma unroll 1
    for (int st = 0; st < STAGES; ++st) {
        char* const base = sm + (st & 1) * BUF_BYTES;

        // ---- store staged regs to smem (A converted to tf32) ----
#pragma unroll
        for (int ci = 0; ci < 2; ++ci)
#pragma unroll
            for (int ii = 0; ii < 4; ++ii) {
                float4 v = apre[ci * 4 + ii];
                uint4 c;
                c.x = f2tf32(v.x); c.y = f2tf32(v.y);
                c.z = f2tf32(v.z); c.w = f2tf32(v.w);
                *(uint4*)(base + ((wr * 4 + ii) * 2 + ci) * 512 + l * 16) = c;
            }
        *(float4*)(base + SM_B_OFF + tid * 16) = bpre[0];
        *(float4*)(base + SM_B_OFF + 4096 + tid * 16) = bpre[1];
        __syncthreads();

        // ---- prefetch next stage ----
        if (st + 1 < STAGES) {
            const float* p = wbase + (size_t)(i00 + (st + 1) * 4) * 16384;
#pragma unroll
            for (int ci = 0; ci < 2; ++ci)
#pragma unroll
                for (int ii = 0; ii < 4; ++ii)
                    apre[ci * 4 + ii] =
                        *(const float4*)(p + (size_t)ii * 16384 + ci * 128);
            const float* q = bbase + (size_t)(st + 1) * 2048;
            bpre[0] = *(const float4*)(q);
            bpre[1] = *(const float4*)(q + 1024);
        }

        // ---- compute this stage: 4 i's x 2 k8-steps x 4 n-tiles ----
#pragma unroll
        for (int ii = 0; ii < 4; ++ii) {
            uint4 va0 = *(const uint4*)(base + ((wr * 4 + ii) * 2 + 0) * 512 + l * 16);
            uint4 va1 = *(const uint4*)(base + ((wr * 4 + ii) * 2 + 1) * 512 + l * 16);
#pragma unroll
            for (int s = 0; s < 2; ++s) {
                uint32_t a0, a1, a2, a3;
                if (s == 0) { a0 = va0.x; a1 = va1.x; a2 = va0.y; a3 = va1.y; }
                else        { a0 = va0.z; a1 = va1.z; a2 = va0.w; a3 = va1.w; }
#pragma unroll
                for (int np = 0; np < 4; ++np) {
                    float2 bb = *(const float2*)(base + SM_B_OFF +
                                                 ((ii * 4 + np) * 2 + s) * 256 + l * 8);
                    mma_tf32(acc[np], a0, a1, a2, a3,
                             __float_as_uint(bb.x), __float_as_uint(bb.y));
                }
            }
        }
        // one sync per iter is sufficient (next STS targets the other buffer)
    }

    // ---- epilogue: D rows g, g+8 of m-tile; cols 2t, 2t+1 of n-tile ----
    const int c0 = cb * 128 + wr * 16 + g;
#pragma unroll
    for (int np = 0; np < 4; ++np) {
        const int b0 = np * 8 + 2 * t;
        g_partial[((size_t)ks * 32 + b0)     * NCOL + c0]     = acc[np].x;
        g_partial[((size_t)ks * 32 + b0 + 1) * NCOL + c0]     = acc[np].y;
        g_partial[((size_t)ks * 32 + b0)     * NCOL + c0 + 8] = acc[np].z;
        g_partial[((size_t)ks * 32 + b0 + 1) * NCOL + c0 + 8] = acc[np].w;
    }
}

// ---------------------------------------------------------------------------
// Reduce K-splits + squash (fused). block = one batch, 1024 threads.
// mag_sq sums over num_units j for each unit_size component k.
// ---------------------------------------------------------------------------
__global__ void k_squash(float* __restrict__ out) {
    const int b = blockIdx.x, c = threadIdx.x;
    float s = 0.f;
#pragma unroll
    for (int ks = 0; ks < KS; ++ks)
        s += g_partial[((size_t)ks * 32 + b) * NCOL + c];

    __shared__ float sd[NCOL];
    __shared__ float mag[USIZE];
    sd[c] = s;
    __syncthreads();
    if (c < USIZE) {
        float m = 0.f;
#pragma unroll
        for (int j = 0; j < NUNITS; ++j) {
            float v = sd[j * USIZE + c];
            m += v * v;
        }
        mag[c] = m;
    }
    __syncthreads();
    const float m = mag[c & (USIZE - 1)];
    out[b * NCOL + c] = s * m / ((1.0f + m) * sqrtf(m));
}

// ---------------------------------------------------------------------------
extern "C" void kernel_launch(void* const* d_in, const int* in_sizes, int n_in,
                              void* d_out, int out_size) {
    const float* x = (const float*)d_in[0];
    const float* W = (const float*)d_in[1];
    if (n_in >= 2 && in_sizes[0] > in_sizes[1]) {
        W = (const float*)d_in[0];
        x = (const float*)d_in[1];
    }
    float* out = (float*)d_out;

    static bool attr_set = false;
    if (!attr_set) {
        cudaFuncSetAttribute(k_main, cudaFuncAttributeMaxDynamicSharedMemorySize,
                             SMEM_TOTAL);
        attr_set = true;
    }

    k_prep<<<4096, 256>>>(x);
    dim3 gm(CBLK, KS);
    k_main<<<gm, 256, SMEM_TOTAL>>>(W);
    k_squash<<<NB, NCOL>>>(out);
}

// round 7
// speedup vs baseline: 3.0680x; 1.3793x over previous
#include <cuda_runtime.h>
#include <cstdint>

// ---------------------------------------------------------------------------
// s[b,c] = sum_{i,u} W[i,c,u] * x[b,u,i]; out = squash(s)
// GEMM: D[M=1024 c][N=32 b] = A[c,k] B[k,b], k = i*16+u, K = 32768
// mma.sync.m16n8k8 tf32 + cp.async 6-stage pipeline (plain sm_103 target).
// ---------------------------------------------------------------------------

#define NB      32
#define NCOL    1024
#define USIZE   64
#define NUNITS  16
#define KS      16        // K-splits (grid.y): 128 i's per CTA
#define CBLK    8         // column blocks of 128 (grid.x)
#define STG     64        // K-stages per CTA; stage = 2 i's = 32 k
#define NS      6         // pipeline depth (smem buffers)

// per-stage smem: A raw fp32 16KB | B frag-ready tf32 4KB
#define BUF_BYTES  20480
#define SM_B_OFF   16384
#define SMEM_TOTAL (NS * BUF_BYTES)

// Scratch (static device globals; no runtime allocation)
__device__ float g_Bfrag[2048 * 512];        // 4 MB: [i][j], j=(np*2+s)*64+l*2+e
__device__ float g_partial[KS * NB * NCOL];  // 2 MB: [ks][b][c]

__device__ __forceinline__ uint32_t f2tf32(float v) {
    uint32_t r;
    asm("cvt.rna.tf32.f32 %0, %1;" : "=r"(r) : "f"(v));
    return r;
}
__device__ __forceinline__ uint32_t smem_u32(const void* p) {
    uint32_t a;
    asm("{ .reg .u64 t; cvta.to.shared.u64 t, %1; cvt.u32.u64 %0, t; }"
        : "=r"(a) : "l"(p));
    return a;
}
__device__ __forceinline__ void cpa16(uint32_t dst, const void* src) {
    asm volatile("cp.async.cg.shared.global [%0], [%1], 16;"
                 :: "r"(dst), "l"(src));
}
#define CP_COMMIT() asm volatile("cp.async.commit_group;" ::: "memory")
#define CP_WAIT(n)  asm volatile("cp.async.wait_group %0;" :: "n"(n) : "memory")

__device__ __forceinline__ void mma_tf32(float4& d,
                                         uint32_t a0, uint32_t a1,
                                         uint32_t a2, uint32_t a3,
                                         uint32_t b0, uint32_t b1) {
    asm volatile(
        "mma.sync.aligned.m16n8k8.row.col.f32.tf32.tf32.f32 "
        "{%0,%1,%2,%3}, {%4,%5,%6,%7}, {%8,%9}, {%0,%1,%2,%3};"
        : "+f"(d.x), "+f"(d.y), "+f"(d.z), "+f"(d.w)
        : "r"(a0), "r"(a1), "r"(a2), "r"(a3), "r"(b0), "r"(b1));
}

// ---------------------------------------------------------------------------
// Prep: x (B,U,IC) -> g_Bfrag[i][j] = tf32(x[b][u][i]),
//   j bits: e=j&1, l=(j>>1)&31, s=(j>>6)&1, np=j>>7; b=8np+(l>>2), u=4(l&3)+2s+e
// smem tile transpose: coalesced reads and writes, <=2-way bank conflicts.
// ---------------------------------------------------------------------------
#define TI 16
__global__ void k_prep(const float* __restrict__ x) {
    __shared__ float t[512][TI + 1];
    const int i0 = blockIdx.x * TI;
    const int tid = threadIdx.x;

    // read: 512 (b,u)-rows x TI i's, 64B segments
#pragma unroll
    for (int it = 0; it < 512 * TI / 256; ++it) {
        int idx = it * 256 + tid;
        int iloc = idx & (TI - 1), bu = idx >> 4;
        int b = bu >> 4, u = bu & 15;
        t[bu][iloc] = x[(size_t)b * 32768 + (size_t)u * 2048 + i0 + iloc];
    }
    __syncthreads();

    // write: coalesced over j; convert to tf32 here
#pragma unroll
    for (int it = 0; it < 512 * TI / 256; ++it) {
        int idx = it * 256 + tid;
        int j = idx & 511, iloc = idx >> 9;
        int e = j & 1, l = (j >> 1) & 31, s = (j >> 6) & 1, np = j >> 7;
        int b = 8 * np + (l >> 2);
        int u = 4 * (l & 3) + 2 * s + e;
        g_Bfrag[(size_t)(i0 + iloc) * 512 + j] =
            __uint_as_float(f2tf32(t[b * 16 + u][iloc]));
    }
}

// ---------------------------------------------------------------------------
// Main GEMM. grid (CBLK, KS), 256 thr = 8 warps; warp wr owns m-rows
// cb*128 + wr*16 .. +16. cp.async 6-stage ring; K = 2048 per CTA.
// ---------------------------------------------------------------------------
__global__ void __launch_bounds__(256, 1) k_main(const float* __restrict__ W) {
    extern __shared__ char sm[];
    const int tid = threadIdx.x;
    const int wr = tid >> 5, l = tid & 31;
    const int g = l >> 2, t4 = l & 3;
    const int cb = blockIdx.x, ks = blockIdx.y;
    const int i00 = ks * 128;

    // issue stage st into ring buffer st%NS
    auto issue = [&](int st) {
        const int ib = i00 + st * 2;
        const uint32_t sa = smem_u32(sm + (st % NS) * BUF_BYTES);
#pragma unroll
        for (int r = 0; r < 4; ++r) {
            const int q = tid + 256 * r;           // 16B chunk id, 0..1023
            const int ii = q >> 9, qi = q & 511;
            cpa16(sa + q * 16,
                  W + (size_t)(ib + ii) * 16384 + cb * 2048 + qi * 4);
        }
        cpa16(sa + SM_B_OFF + tid * 16, g_Bfrag + (size_t)ib * 512 + tid * 4);
    };

#pragma unroll
    for (int st = 0; st < NS - 1; ++st) { issue(st); CP_COMMIT(); }

    float4 acc[4];
#pragma unroll
    for (int np = 0; np < 4; ++np) acc[np] = make_float4(0.f, 0.f, 0.f, 0.f);

    const int arow0 = (wr * 16 + g) * 4 + t4;        // 16B chunk within i-slab
    const int arow1 = (wr * 16 + 8 + g) * 4 + t4;

#pragma unroll 1
    for (int st = 0; st < STG; ++st) {
        CP_WAIT(NS - 2);
        __syncthreads();

        char* const buf = sm + (st % NS) * BUF_BYTES;
#pragma unroll
        for (int ii = 0; ii < 2; ++ii) {
            uint4 r0 = *(const uint4*)(buf + (ii * 512 + arow0) * 16);
            uint4 r1 = *(const uint4*)(buf + (ii * 512 + arow1) * 16);
            uint32_t a[8];
            a[0] = f2tf32(__uint_as_float(r0.x));
            a[1] = f2tf32(__uint_as_float(r1.x));
            a[2] = f2tf32(__uint_as_float(r0.y));
            a[3] = f2tf32(__uint_as_float(r1.y));
            a[4] = f2tf32(__uint_as_float(r0.z));
            a[5] = f2tf32(__uint_as_float(r1.z));
            a[6] = f2tf32(__uint_as_float(r0.w));
            a[7] = f2tf32(__uint_as_float(r1.w));
#pragma unroll
            for (int s = 0; s < 2; ++s) {
                const uint32_t a0 = a[s * 4 + 0], a1 = a[s * 4 + 1];
                const uint32_t a2 = a[s * 4 + 2], a3 = a[s * 4 + 3];
#pragma unroll
                for (int np = 0; np < 4; ++np) {
                    float2 bb = *(const float2*)(buf + SM_B_OFF + ii * 2048 +
                                                 ((np * 2 + s) * 64 + l * 2) * 4);
                    mma_tf32(acc[np], a0, a1, a2, a3,
                             __float_as_uint(bb.x), __float_as_uint(bb.y));
                }
            }
        }

        // issue stage st+NS-1 (safe: barrier above proves all done with st-1)
        if (st + NS - 1 < STG) issue(st + NS - 1);
        CP_COMMIT();   // always commit to keep group accounting aligned
    }

    // epilogue: rows g/g+8 of m-tile, cols 2t4/2t4+1 of each n-tile
    const int c0 = cb * 128 + wr * 16 + g;
#pragma unroll
    for (int np = 0; np < 4; ++np) {
        const int b0 = np * 8 + 2 * t4;
        g_partial[((size_t)ks * 32 + b0)     * NCOL + c0]     = acc[np].x;
        g_partial[((size_t)ks * 32 + b0 + 1) * NCOL + c0]     = acc[np].y;
        g_partial[((size_t)ks * 32 + b0)     * NCOL + c0 + 8] = acc[np].z;
        g_partial[((size_t)ks * 32 + b0 + 1) * NCOL + c0 + 8] = acc[np].w;
    }
}

// ---------------------------------------------------------------------------
// Reduce K-splits + squash (fused). block = one batch, 1024 threads.
// ---------------------------------------------------------------------------
__global__ void k_squash(float* __restrict__ out) {
    const int b = blockIdx.x, c = threadIdx.x;
    float s = 0.f;
#pragma unroll
    for (int ks = 0; ks < KS; ++ks)
        s += g_partial[((size_t)ks * 32 + b) * NCOL + c];

    __shared__ float sd[NCOL];
    __shared__ float mag[USIZE];
    sd[c] = s;
    __syncthreads();
    if (c < USIZE) {
        float m = 0.f;
#pragma unroll
        for (int j = 0; j < NUNITS; ++j) {
            float v = sd[j * USIZE + c];
            m += v * v;
        }
        mag[c] = m;
    }
    __syncthreads();
    const float m = mag[c & (USIZE - 1)];
    out[b * NCOL + c] = s * m / ((1.0f + m) * sqrtf(m));
}

// ---------------------------------------------------------------------------
extern "C" void kernel_launch(void* const* d_in, const int* in_sizes, int n_in,
                              void* d_out, int out_size) {
    const float* x = (const float*)d_in[0];
    const float* W = (const float*)d_in[1];
    if (n_in >= 2 && in_sizes[0] > in_sizes[1]) {
        W = (const float*)d_in[0];
        x = (const float*)d_in[1];
    }
    float* out = (float*)d_out;

    static bool attr_set = false;
    if (!attr_set) {
        cudaFuncSetAttribute(k_main, cudaFuncAttributeMaxDynamicSharedMemorySize,
                             SMEM_TOTAL);
        attr_set = true;
    }

    k_prep<<<2048 / TI, 256>>>(x);
    dim3 gm(CBLK, KS);
    k_main<<<gm, 256, SMEM_TOTAL>>>(W);
    k_squash<<<NB, NCOL>>>(out);
}

// round 8
// speedup vs baseline: 3.2475x; 1.0585x over previous
#include <cuda_runtime.h>
#include <cstdint>

// ---------------------------------------------------------------------------
// s[b,c] = sum_{i,u} W[i,c,u] * x[b,u,i]; out = squash(s)
// GEMM: D[M=1024 c][N=32 b] = A[c,k] B[k,b], k = i*16+u, K = 32768
// mma.sync.m16n8k8 tf32 + cp.async 5-stage pipeline, 2 CTAs/SM.
// ---------------------------------------------------------------------------

#define NB      32
#define NCOL    1024
#define USIZE   64
#define NUNITS  16
#define KS      32        // K-splits (grid.y): 64 i's per CTA
#define CBLK    8         // column blocks of 128 (grid.x)
#define STG     32        // K-stages per CTA; stage = 2 i's = 32 k
#define NS      5         // pipeline depth (smem buffers)

// per-stage smem: A raw fp32 16KB | B frag-ready tf32 4KB
#define BUF_BYTES  20480
#define SM_B_OFF   16384
#define SMEM_TOTAL (NS * BUF_BYTES)     // 100 KB -> 2 CTAs/SM

// Scratch (static device globals; no runtime allocation)
__device__ float g_Bfrag[2048 * 512];        // 4 MB: [i][j], j=(np*2+s)*64+l*2+e
__device__ float g_partial[KS * NB * NCOL];  // 4 MB: [ks][b][c]

__device__ __forceinline__ uint32_t f2tf32(float v) {
    uint32_t r;
    asm("cvt.rna.tf32.f32 %0, %1;" : "=r"(r) : "f"(v));
    return r;
}
__device__ __forceinline__ uint32_t smem_u32(const void* p) {
    uint32_t a;
    asm("{ .reg .u64 t; cvta.to.shared.u64 t, %1; cvt.u32.u64 %0, t; }"
        : "=r"(a) : "l"(p));
    return a;
}
__device__ __forceinline__ void cpa16(uint32_t dst, const void* src) {
    asm volatile("cp.async.cg.shared.global [%0], [%1], 16;"
                 :: "r"(dst), "l"(src));
}
#define CP_COMMIT() asm volatile("cp.async.commit_group;" ::: "memory")
#define CP_WAIT(n)  asm volatile("cp.async.wait_group %0;" :: "n"(n) : "memory")

__device__ __forceinline__ void mma_tf32(float4& d,
                                         uint32_t a0, uint32_t a1,
                                         uint32_t a2, uint32_t a3,
                                         uint32_t b0, uint32_t b1) {
    asm volatile(
        "mma.sync.aligned.m16n8k8.row.col.f32.tf32.tf32.f32 "
        "{%0,%1,%2,%3}, {%4,%5,%6,%7}, {%8,%9}, {%0,%1,%2,%3};"
        : "+f"(d.x), "+f"(d.y), "+f"(d.z), "+f"(d.w)
        : "r"(a0), "r"(a1), "r"(a2), "r"(a3), "r"(b0), "r"(b1));
}

// ---------------------------------------------------------------------------
// Prep: x (B,U,IC) -> g_Bfrag[i][j] = tf32(x[b][u][i])
//   j bits: e=j&1, l=(j>>1)&31, s=(j>>6)&1, np=j>>7; b=8np+(l>>2), u=4(l&3)+2s+e
// grid = (i-tiles 128) x (np 4): small smem tiles, high occupancy, both sides
// coalesced. 8 MB total traffic -> should be ~1.5-2 us.
// ---------------------------------------------------------------------------
__global__ void __launch_bounds__(256) k_prep(const float* __restrict__ x) {
    __shared__ float t[128][17];            // row = g*16+u (g = b&7), col = iloc
    const int i0 = (blockIdx.x >> 2) * 16;
    const int np = blockIdx.x & 3;
    const int tid = threadIdx.x;

    // read: 128 (b,u)-rows x 16 i's, 64B coalesced segments
#pragma unroll
    for (int it = 0; it < 8; ++it) {
        int idx = it * 256 + tid;           // 0..2047
        int iloc = idx & 15, r = idx >> 4;  // r = g*16+u
        int b = 8 * np + (r >> 4), u = r & 15;
        t[r][iloc] = x[(size_t)b * 32768 + (size_t)u * 2048 + i0 + iloc];
    }
    __syncthreads();

    // write: for each i, the contiguous 128-j chunk owned by this np
#pragma unroll
    for (int it = 0; it < 8; ++it) {
        int idx = it * 256 + tid;
        int jloc = idx & 127, iloc = idx >> 7;
        int j = np * 128 + jloc;
        int e = j & 1, l = (j >> 1) & 31, s = (j >> 6) & 1;
        int r = (l >> 2) * 16 + 4 * (l & 3) + 2 * s + e;
        g_Bfrag[(size_t)(i0 + iloc) * 512 + j] =
            __uint_as_float(f2tf32(t[r][iloc]));
    }
}

// ---------------------------------------------------------------------------
// Main GEMM. grid (CBLK, KS), 256 thr = 8 warps; warp wr owns m-rows
// cb*128 + wr*16 .. +16. cp.async 5-stage ring; K = 1024 per CTA. 2 CTAs/SM.
// ---------------------------------------------------------------------------
__global__ void __launch_bounds__(256, 2) k_main(const float* __restrict__ W) {
    extern __shared__ char sm[];
    const int tid = threadIdx.x;
    const int wr = tid >> 5, l = tid & 31;
    const int g = l >> 2, t4 = l & 3;
    const int cb = blockIdx.x, ks = blockIdx.y;
    const int i00 = ks * 64;

    // issue stage st into ring buffer st%NS
    auto issue = [&](int st) {
        const int ib = i00 + st * 2;
        const uint32_t sa = smem_u32(sm + (st % NS) * BUF_BYTES);
#pragma unroll
        for (int r = 0; r < 4; ++r) {
            const int q = tid + 256 * r;           // 16B chunk id, 0..1023
            const int ii = q >> 9, qi = q & 511;
            cpa16(sa + q * 16,
                  W + (size_t)(ib + ii) * 16384 + cb * 2048 + qi * 4);
        }
        cpa16(sa + SM_B_OFF + tid * 16, g_Bfrag + (size_t)ib * 512 + tid * 4);
    };

#pragma unroll
    for (int st = 0; st < NS - 1; ++st) { issue(st); CP_COMMIT(); }

    float4 acc[4];
#pragma unroll
    for (int np = 0; np < 4; ++np) acc[np] = make_float4(0.f, 0.f, 0.f, 0.f);

    const int arow0 = (wr * 16 + g) * 4 + t4;        // 16B chunk within i-slab
    const int arow1 = (wr * 16 + 8 + g) * 4 + t4;

#pragma unroll 1
    for (int st = 0; st < STG; ++st) {
        CP_WAIT(NS - 2);
        __syncthreads();

        char* const buf = sm + (st % NS) * BUF_BYTES;
#pragma unroll
        for (int ii = 0; ii < 2; ++ii) {
            uint4 r0 = *(const uint4*)(buf + (ii * 512 + arow0) * 16);
            uint4 r1 = *(const uint4*)(buf + (ii * 512 + arow1) * 16);
            uint32_t a[8];
            a[0] = f2tf32(__uint_as_float(r0.x));
            a[1] = f2tf32(__uint_as_float(r1.x));
            a[2] = f2tf32(__uint_as_float(r0.y));
            a[3] = f2tf32(__uint_as_float(r1.y));
            a[4] = f2tf32(__uint_as_float(r0.z));
            a[5] = f2tf32(__uint_as_float(r1.z));
            a[6] = f2tf32(__uint_as_float(r0.w));
            a[7] = f2tf32(__uint_as_float(r1.w));
#pragma unroll
            for (int s = 0; s < 2; ++s) {
                const uint32_t a0 = a[s * 4 + 0], a1 = a[s * 4 + 1];
                const uint32_t a2 = a[s * 4 + 2], a3 = a[s * 4 + 3];
#pragma unroll
                for (int np = 0; np < 4; ++np) {
                    float2 bb = *(const float2*)(buf + SM_B_OFF + ii * 2048 +
                                                 ((np * 2 + s) * 64 + l * 2) * 4);
                    mma_tf32(acc[np], a0, a1, a2, a3,
                             __float_as_uint(bb.x), __float_as_uint(bb.y));
                }
            }
        }

        // issue stage st+NS-1 (safe: barrier above proves all done with st-1)
        if (st + NS - 1 < STG) issue(st + NS - 1);
        CP_COMMIT();   // always commit to keep group accounting aligned
    }

    // epilogue: rows g/g+8 of m-tile, cols 2t4/2t4+1 of each n-tile
    const int c0 = cb * 128 + wr * 16 + g;
#pragma unroll
    for (int np = 0; np < 4; ++np) {
        const int b0 = np * 8 + 2 * t4;
        g_partial[((size_t)ks * 32 + b0)     * NCOL + c0]     = acc[np].x;
        g_partial[((size_t)ks * 32 + b0 + 1) * NCOL + c0]     = acc[np].y;
        g_partial[((size_t)ks * 32 + b0)     * NCOL + c0 + 8] = acc[np].z;
        g_partial[((size_t)ks * 32 + b0 + 1) * NCOL + c0 + 8] = acc[np].w;
    }
}

// ---------------------------------------------------------------------------
// Reduce K-splits + squash (fused). block = one batch, 1024 threads.
// ---------------------------------------------------------------------------
__global__ void k_squash(float* __restrict__ out) {
    const int b = blockIdx.x, c = threadIdx.x;
    float s = 0.f;
#pragma unroll
    for (int ks = 0; ks < KS; ++ks)
        s += g_partial[((size_t)ks * 32 + b) * NCOL + c];

    __shared__ float sd[NCOL];
    __shared__ float mag[USIZE];
    sd[c] = s;
    __syncthreads();
    if (c < USIZE) {
        float m = 0.f;
#pragma unroll
        for (int j = 0; j < NUNITS; ++j) {
            float v = sd[j * USIZE + c];
            m += v * v;
        }
        mag[c] = m;
    }
    __syncthreads();
    const float m = mag[c & (USIZE - 1)];
    out[b * NCOL + c] = s * m / ((1.0f + m) * sqrtf(m));
}

// ---------------------------------------------------------------------------
extern "C" void kernel_launch(void* const* d_in, const int* in_sizes, int n_in,
                              void* d_out, int out_size) {
    const float* x = (const float*)d_in[0];
    const float* W = (const float*)d_in[1];
    if (n_in >= 2 && in_sizes[0] > in_sizes[1]) {
        W = (const float*)d_in[0];
        x = (const float*)d_in[1];
    }
    float* out = (float*)d_out;

    static bool attr_set = false;
    if (!attr_set) {
        cudaFuncSetAttribute(k_main, cudaFuncAttributeMaxDynamicSharedMemorySize,
                             SMEM_TOTAL);
        attr_set = true;
    }

    k_prep<<<512, 256>>>(x);
    dim3 gm(CBLK, KS);
    k_main<<<gm, 256, SMEM_TOTAL>>>(W);
    k_squash<<<NB, NCOL>>>(out);
}